// round 8
// baseline (speedup 1.0000x reference)
#include <cuda_runtime.h>
#include <math.h>

#define D_      100
#define DH_     50
#define B_      512
#define G_      3
#define NTAB    100000
#define DIN_    200
#define PP      204           // floats per row-pair: 100 k * 2 + 4 pad

__device__ float g_spec[B_ * G_ * D_];

typedef unsigned long long ull;

__device__ __forceinline__ ull pk2(float lo, float hi) {
    ull r; asm("mov.b64 %0, {%1, %2};" : "=l"(r) : "f"(lo), "f"(hi)); return r;
}
__device__ __forceinline__ float2 upk2(ull v) {
    float2 f; asm("mov.b64 {%0, %1}, %2;" : "=f"(f.x), "=f"(f.y) : "l"(v)); return f;
}
#define FMA2(acc, a, b) asm("fma.rn.f32x2 %0, %1, %2, %0;" : "+l"(acc) : "l"(a), "l"(b))

__device__ __forceinline__ float bsum384(float v, float* red, int tid) {
    __syncthreads();
#pragma unroll
    for (int o = 16; o; o >>= 1) v += __shfl_xor_sync(0xffffffffu, v, o);
    if ((tid & 31) == 0) red[tid >> 5] = v;
    __syncthreads();
    if (tid == 0) {
        float s = 0.f;
#pragma unroll
        for (int w = 0; w < 12; w++) s += red[w];
        red[0] = s;
    }
    __syncthreads();
    return red[0];
}

// mean of S gathered rows -> pair-major tile slot m (= mbase + mo)
template<int S>
__device__ __forceinline__ void mean_rows(const float4* e4, const int* grp, float* sT,
                                          int mbase, int count, int tid) {
    const int range = ((count + 3) >> 2) << 7;
    const float c = 1.f / (float)S;
    for (int idx = tid; idx < range; idx += 384) {
        int qs = (idx >> 2) & 31;
        int mo = ((idx >> 7) << 2) + (idx & 3);
        if (qs >= 25 || mo >= count) continue;
        const int* np = grp + mo * S;
        float ax = 0.f, ay = 0.f, az = 0.f, aw = 0.f;
#pragma unroll
        for (int s = 0; s < S; s++) {
            float4 v = e4[(size_t)np[s] * 25 + qs];
            ax += v.x; ay += v.y; az += v.z; aw += v.w;
        }
        int m = mbase + mo;
        float* dst = sT + (m >> 1) * PP + 8 * qs + (m & 1);
        dst[0] = ax * c; dst[2] = ay * c; dst[4] = az * c; dst[6] = aw * c;
    }
}

// ===================== fused GraphSage: one block per (b,g) =====================
// smem floats: sA 62*204=12648 | sMn 62*204=12648 | idx 1072 | red 16
#define SM_A    0
#define SM_M    12648
#define SM_IDX  25296
#define SM_RED  26368
#define FUSED_SMEM ((26368 + 16) * 4)

__global__ __launch_bounds__(384, 2)
void fused_sage(const float* __restrict__ emb,
                const int* __restrict__ nodeids,
                const int* __restrict__ n0, const int* __restrict__ n1,
                const int* __restrict__ n2, const int* __restrict__ n3,
                const float* __restrict__ Wself, const float* __restrict__ Wneigh,
                const float* __restrict__ bself, const float* __restrict__ bneigh,
                const float* __restrict__ Wfc, const float* __restrict__ bfc,
                float* __restrict__ spec_out)
{
    extern __shared__ float sm[];
    float* sA   = sm + SM_A;       // pair-major self tile; later g0 [124][100]
    float* sMn  = sm + SM_M;       // pair-major means tile; later tail bufs
    int*   sIdx = (int*)(sm + SM_IDX);
    float* red  = sm + SM_RED;

    const int b = blockIdx.x, g = blockIdx.y, tid = threadIdx.x;

    // indices: [0]=seed, [1..3]=n0, [4..18]=n1, [19..123]=n2, [124..1068]=n3
    if (tid == 0)  sIdx[0] = nodeids[b];
    if (tid < 3)   sIdx[1 + tid]  = n0[g * 1536  + 3 * b   + tid];
    if (tid < 15)  sIdx[4 + tid]  = n1[g * 7680  + 15 * b  + tid];
    if (tid < 105) sIdx[19 + tid] = n2[g * 53760 + 105 * b + tid];
    for (int i = tid; i < 945; i += 384) sIdx[124 + i] = n3[(size_t)g * 483840 + 945 * b + i];
    __syncthreads();

    const float4* e4 = (const float4*)(emb + (size_t)g * NTAB * D_);

    // ---- self gather: 62 pairs, ull stores (2-way banks) ----
    for (int idx = tid; idx < 2048; idx += 384) {
        int qs = (idx >> 2) & 31;
        int p  = ((idx >> 7) << 2) + (idx & 3);
        if (qs >= 25 || p >= 62) continue;
        float4 va = e4[(size_t)sIdx[2 * p]     * 25 + qs];
        float4 vb = e4[(size_t)sIdx[2 * p + 1] * 25 + qs];
        ull* dst = (ull*)(sA + p * PP + 8 * qs);
        dst[0] = pk2(va.x, vb.x);
        dst[1] = pk2(va.y, vb.y);
        dst[2] = pk2(va.z, vb.z);
        dst[3] = pk2(va.w, vb.w);
    }
    // ---- neighbor means ----
    mean_rows<3>(e4, sIdx + 1,   sMn, 0,  1,   tid);
    mean_rows<5>(e4, sIdx + 4,   sMn, 1,  3,   tid);
    mean_rows<7>(e4, sIdx + 19,  sMn, 4,  15,  tid);
    mean_rows<9>(e4, sIdx + 124, sMn, 19, 105, tid);
    __syncthreads();

    // ---- pass 0 GEMM: 350 threads, 2 cols x 9 pairs, float4 feeds 2 k's ----
    ull acc0[9], acc1[9];
    int j0 = 0, rt = 0;
    if (tid < 350) {
        const int ct = tid % 50; rt = tid / 50;
        j0 = 2 * ct;
        const bool selfh = (j0 < DH_);
        const int jj = selfh ? j0 : j0 - DH_;
        const float* aT = (selfh ? sA : sMn) + rt * 9 * PP;
        const float* Wp = (selfh ? Wself : Wneigh) + (size_t)(g * 4) * 5000 + jj;
        const float* bp = (selfh ? bself : bneigh) + (g * 4) * DH_;
        {
            float b0 = bp[jj], b1 = bp[jj + 1];
            ull bb0 = pk2(b0, b0), bb1 = pk2(b1, b1);
#pragma unroll
            for (int p = 0; p < 9; p++) { acc0[p] = bb0; acc1[p] = bb1; }
        }
#pragma unroll 5
        for (int k0 = 0; k0 < 100; k0 += 2) {
            float2 wa = __ldg((const float2*)(Wp + k0 * DH_));
            float2 wb = __ldg((const float2*)(Wp + (k0 + 1) * DH_));
            ull wa0 = pk2(wa.x, wa.x), wa1 = pk2(wa.y, wa.y);
            ull wb0 = pk2(wb.x, wb.x), wb1 = pk2(wb.y, wb.y);
            const float* ak = aT + 2 * k0;
#pragma unroll
            for (int p = 0; p < 9; p++) {
                float4 x = *(const float4*)(ak + p * PP);
                ull xk  = pk2(x.x, x.y);   // k0:   rows 2p, 2p+1
                ull xk1 = pk2(x.z, x.w);   // k0+1
                FMA2(acc0[p], xk,  wa0);
                FMA2(acc1[p], xk,  wa1);
                FMA2(acc0[p], xk1, wb0);
                FMA2(acc1[p], xk1, wb1);
            }
        }
    }
    __syncthreads();
    // write g0 row-major [124][100] into sA
    if (tid < 350) {
#pragma unroll
        for (int p = 0; p < 9; p++) {
            int pr = rt * 9 + p;
            if (pr < 62) {
                float2 v0 = upk2(acc0[p]);   // (row even, row odd) col j0
                float2 v1 = upk2(acc1[p]);   // col j0+1
                float2 t0; t0.x = fmaxf(v0.x, 0.f); t0.y = fmaxf(v1.x, 0.f);
                float2 t1; t1.x = fmaxf(v0.y, 0.f); t1.y = fmaxf(v1.y, 0.f);
                *(float2*)(sA + (2 * pr)     * 100 + j0) = t0;
                *(float2*)(sA + (2 * pr + 1) * 100 + j0) = t1;
            }
        }
    }
    __syncthreads();

    // ---- tail buffers in sMn region ----
    float* sFT = sMn;          // [j][20]
    float* sMT = sMn + 2000;   // [j][20]
    float* sMG = sMn + 4000;   // [j][4]
    float* sG2 = sMn + 4400;   // [j][4]
    float* sM3 = sMn + 4816;   // [100]
    float* sG3 = sMn + 4920;   // [104]

    for (int i = tid; i < 1900; i += 384) {
        int r = i / 100, j = i - r * 100;
        sFT[j * 20 + r] = sA[r * 100 + j];
    }
    for (int i = tid; i < 1500; i += 384) {
        int r = i / 100, j = i - r * 100;
        const float* p = sA + (19 + 7 * r) * 100 + j;
        float a = p[0];
#pragma unroll
        for (int s = 1; s < 7; s++) a += p[s * 100];
        sMT[j * 20 + 4 + r] = a * (1.f / 7.f);
    }
    if (tid < 100) { sFT[tid * 20 + 19] = 0.f; sMT[tid * 20 + 19] = 0.f; }
    __syncthreads();
    for (int i = tid; i < 400; i += 384) {
        int r = i / 100, j = i - r * 100;
        const float* col = sFT + j * 20;
        float a;
        if (r == 0) a = (col[1] + col[2] + col[3]) * (1.f / 3.f);
        else {
            int q = 4 + 5 * (r - 1);
            a = (col[q] + col[q + 1] + col[q + 2] + col[q + 3] + col[q + 4]) * 0.2f;
        }
        sMT[j * 20 + r] = a;
    }
    __syncthreads();

    const bool act   = (tid < 100);
    const bool selfh = (tid < 50);
    const int  jj    = selfh ? tid : tid - 50;

    // ---- pass 1 ----
    ull acc1t[10];
    {
        const float* Wp = (selfh ? Wself : Wneigh) + (size_t)(g * 4 + 1) * 5000 + jj;
        const float* srcp = selfh ? sFT : sMT;
        float bias = act ? (selfh ? bself[(g * 4 + 1) * 50 + jj] : bneigh[(g * 4 + 1) * 50 + jj]) : 0.f;
        ull b2 = pk2(bias, bias);
#pragma unroll
        for (int p = 0; p < 10; p++) acc1t[p] = b2;
        if (act) {
#pragma unroll
            for (int k0 = 0; k0 < 100; k0 += 5) {
                float wv[5];
#pragma unroll
                for (int i = 0; i < 5; i++) wv[i] = __ldg(Wp + (k0 + i) * 50);
#pragma unroll
                for (int i = 0; i < 5; i++) {
                    ull w2 = pk2(wv[i], wv[i]);
                    const float4* xr = (const float4*)(srcp + (k0 + i) * 20);
#pragma unroll
                    for (int q = 0; q < 5; q++) {
                        float4 xv = xr[q];
                        FMA2(acc1t[2 * q],     pk2(xv.x, xv.y), w2);
                        FMA2(acc1t[2 * q + 1], pk2(xv.z, xv.w), w2);
                    }
                }
            }
        }
    }
    __syncthreads();
    if (act) {
        float* o = sFT + tid * 20;
#pragma unroll
        for (int p = 0; p < 10; p++) {
            float2 v = upk2(acc1t[p]);
            o[2 * p] = fmaxf(v.x, 0.f);
            if (2 * p + 1 < 19) o[2 * p + 1] = fmaxf(v.y, 0.f);
        }
        o[19] = 0.f;
    }
    __syncthreads();

    // ---- pass 2 means ----
    if (act) {
        const float* col = sFT + tid * 20;
        float* mg = sMG + tid * 4;
        mg[0] = (col[1] + col[2] + col[3]) * (1.f / 3.f);
#pragma unroll
        for (int r = 0; r < 3; r++) {
            int q = 4 + 5 * r;
            mg[1 + r] = (col[q] + col[q + 1] + col[q + 2] + col[q + 3] + col[q + 4]) * 0.2f;
        }
    }
    __syncthreads();

    // ---- pass 2 ----
    {
        const float* Wp = (selfh ? Wself : Wneigh) + (size_t)(g * 4 + 2) * 5000 + jj;
        const float* srcp = selfh ? sFT : sMG;
        const int pitch = selfh ? 20 : 4;
        float bias = act ? (selfh ? bself[(g * 4 + 2) * 50 + jj] : bneigh[(g * 4 + 2) * 50 + jj]) : 0.f;
        ull a0 = pk2(bias, bias), a1 = a0;
        if (act) {
#pragma unroll
            for (int k0 = 0; k0 < 100; k0 += 10) {
                float wv[10];
#pragma unroll
                for (int i = 0; i < 10; i++) wv[i] = __ldg(Wp + (k0 + i) * 50);
#pragma unroll
                for (int i = 0; i < 10; i++) {
                    ull w2 = pk2(wv[i], wv[i]);
                    float4 xv = *(const float4*)(srcp + (k0 + i) * pitch);
                    FMA2(a0, pk2(xv.x, xv.y), w2);
                    FMA2(a1, pk2(xv.z, xv.w), w2);
                }
            }
            float* o = sG2 + tid * 4;
            float2 v0 = upk2(a0), v1 = upk2(a1);
            o[0] = fmaxf(v0.x, 0.f); o[1] = fmaxf(v0.y, 0.f);
            o[2] = fmaxf(v1.x, 0.f); o[3] = fmaxf(v1.y, 0.f);
        }
    }
    __syncthreads();

    if (act)
        sM3[tid] = (sG2[tid * 4 + 1] + sG2[tid * 4 + 2] + sG2[tid * 4 + 3]) * (1.f / 3.f);
    __syncthreads();

    // ---- pass 3 + l2norm ----
    float g3 = 0.f;
    if (act) {
        const float* Wp = (selfh ? Wself : Wneigh) + (size_t)(g * 4 + 3) * 5000 + jj;
        float a = selfh ? bself[(g * 4 + 3) * 50 + jj] : bneigh[(g * 4 + 3) * 50 + jj];
#pragma unroll
        for (int k0 = 0; k0 < 100; k0 += 10) {
            float wv[10];
#pragma unroll
            for (int i = 0; i < 10; i++) wv[i] = __ldg(Wp + (k0 + i) * 50);
#pragma unroll
            for (int i = 0; i < 10; i++) {
                float x = selfh ? sG2[(k0 + i) * 4] : sM3[k0 + i];
                a += x * wv[i];
            }
        }
        g3 = fmaxf(a, 0.f);
        sG3[tid] = g3;
    }
    float ss = bsum384(act ? g3 * g3 : 0.f, red, tid);
    float s_inv = 1.f / fmaxf(sqrtf(ss), 1e-12f);

    // ---- FC -> spec ----
    if (act) {
        const float* Wf = Wfc + (size_t)g * 10000 + tid;
        float a = 0.f;
#pragma unroll
        for (int k0 = 0; k0 < 100; k0 += 10) {
            float wv[10];
#pragma unroll
            for (int i = 0; i < 10; i++) wv[i] = __ldg(Wf + (k0 + i) * 100);
#pragma unroll
            for (int i = 0; i < 10; i++) a += sG3[k0 + i] * wv[i];
        }
        spec_out[(size_t)(b * 3 + g) * 100 + tid] = a * s_inv + bfc[g * 100 + tid];
    }
}

// ===================== attention + reflect, one block per seed =====================
__global__ __launch_bounds__(384)
void attn_kernel(const float* __restrict__ spec_in,
                 const int* __restrict__ nodeids, const int* __restrict__ edgetypes,
                 const float* __restrict__ base,
                 const float* __restrict__ lng, const float* __restrict__ lnb,
                 const float* __restrict__ Wq, const float* __restrict__ Wk,
                 const float* __restrict__ Wv, const float* __restrict__ Wo,
                 const float* __restrict__ reflect, float* __restrict__ out)
{
    __shared__ float spec[300];
    __shared__ float qn[100], Qs[100], Ks[300], Vs[300], ctx[100], sel[100];
    __shared__ float tmp[DIN_];
    __shared__ float red[12], sc[3];

    const int b = blockIdx.x, tid = threadIdx.x;

    for (int i = tid; i < 300; i += 384) spec[i] = spec_in[(size_t)b * 300 + i];
    __syncthreads();

    const int et = edgetypes[b];

    float x = (tid < 100) ? spec[et * 100 + tid] : 0.f;
    float mu = bsum384(x, red, tid) * 0.01f;
    float dd = (tid < 100) ? (x - mu) : 0.f;
    float var = bsum384(dd * dd, red, tid) * 0.01f;
    if (tid < 100) qn[tid] = dd * rsqrtf(var + 1e-6f) * lng[tid] + lnb[tid];
    __syncthreads();

    if (tid < 100) {
        float aq = 0.f;
#pragma unroll
        for (int k0 = 0; k0 < 100; k0 += 10) {
            float wv[10];
#pragma unroll
            for (int i = 0; i < 10; i++) wv[i] = __ldg(Wq + (k0 + i) * 100 + tid);
#pragma unroll
            for (int i = 0; i < 10; i++) aq += qn[k0 + i] * wv[i];
        }
        Qs[tid] = aq;
    }
    if (tid < 300) {
        int h = tid / 100, j = tid - h * 100;
        const float* sp = spec + h * 100;
        float ak = 0.f, av = 0.f;
#pragma unroll
        for (int k0 = 0; k0 < 100; k0 += 10) {
            float wk[10], wv[10];
#pragma unroll
            for (int i = 0; i < 10; i++) {
                wk[i] = __ldg(Wk + (k0 + i) * 100 + j);
                wv[i] = __ldg(Wv + (k0 + i) * 100 + j);
            }
#pragma unroll
            for (int i = 0; i < 10; i++) {
                float s = sp[k0 + i];
                ak += s * wk[i];
                av += s * wv[i];
            }
        }
        Ks[h * 100 + j] = ak;
        Vs[h * 100 + j] = av;
    }
    __syncthreads();

    for (int h = 0; h < 3; h++) {
        float p = (tid < 100) ? Qs[tid] * Ks[h * 100 + tid] : 0.f;
        float s = bsum384(p, red, tid);
        if (tid == 0) sc[h] = s * 0.1f;
    }
    __syncthreads();
    {
        float m = fmaxf(sc[0], fmaxf(sc[1], sc[2]));
        float e0 = expf(sc[0] - m), e1 = expf(sc[1] - m), e2 = expf(sc[2] - m);
        float inv = 1.f / (e0 + e1 + e2);
        float a0 = e0 * inv, a1 = e1 * inv, a2 = e2 * inv;
        if (tid < 100)
            ctx[tid] = a0 * Vs[tid] + a1 * Vs[100 + tid] + a2 * Vs[200 + tid];
    }
    __syncthreads();
    if (tid < 100) {
        float a = spec[et * 100 + tid];
#pragma unroll
        for (int k0 = 0; k0 < 100; k0 += 10) {
            float wv[10];
#pragma unroll
            for (int i = 0; i < 10; i++) wv[i] = __ldg(Wo + (k0 + i) * 100 + tid);
#pragma unroll
            for (int i = 0; i < 10; i++) a += ctx[k0 + i] * wv[i];
        }
        sel[tid] = a;
    }
    __syncthreads();

    const int nid = nodeids[b];
    const float* R = reflect + (size_t)et * 100 * DIN_;
    float lss = 0.f;
    if (tid < DIN_) {
        float a = 0.f;
#pragma unroll
        for (int k0 = 0; k0 < 100; k0 += 10) {
            float wv[10];
#pragma unroll
            for (int i = 0; i < 10; i++) wv[i] = __ldg(R + (k0 + i) * DIN_ + tid);
#pragma unroll
            for (int i = 0; i < 10; i++) a += sel[k0 + i] * wv[i];
        }
        float r = base[(size_t)nid * DIN_ + tid] + a;
        tmp[tid] = r;
        lss = r * r;
    }
    float ss = bsum384(lss, red, tid);
    float sca = 1.f / fmaxf(sqrtf(ss), 1e-12f);
    if (tid < DIN_) out[(size_t)b * DIN_ + tid] = tmp[tid] * sca;
}

extern "C" void kernel_launch(void* const* d_in, const int* in_sizes, int n_in,
                              void* d_out, int out_size) {
    const int*   nodeids   = (const int*)d_in[0];
    const int*   edgetypes = (const int*)d_in[1];
    const int*   n0        = (const int*)d_in[2];
    const int*   n1        = (const int*)d_in[3];
    const int*   n2        = (const int*)d_in[4];
    const int*   n3        = (const int*)d_in[5];
    const float* base      = (const float*)d_in[6];
    const float* emb       = (const float*)d_in[7];
    const float* Wself     = (const float*)d_in[8];
    const float* bself     = (const float*)d_in[9];
    const float* Wneigh    = (const float*)d_in[10];
    const float* bneigh    = (const float*)d_in[11];
    const float* Wfc       = (const float*)d_in[12];
    const float* bfc       = (const float*)d_in[13];
    const float* lng       = (const float*)d_in[14];
    const float* lnb       = (const float*)d_in[15];
    const float* Wq        = (const float*)d_in[16];
    const float* Wk        = (const float*)d_in[17];
    const float* Wv        = (const float*)d_in[18];
    const float* Wo        = (const float*)d_in[19];
    const float* reflect   = (const float*)d_in[20];
    float* out = (float*)d_out;

    float* spec;
    cudaGetSymbolAddress((void**)&spec, g_spec);

    cudaFuncSetAttribute(fused_sage, cudaFuncAttributeMaxDynamicSharedMemorySize, FUSED_SMEM);

    fused_sage<<<dim3(B_, G_), 384, FUSED_SMEM>>>(emb, nodeids, n0, n1, n2, n3,
                                                  Wself, Wneigh, bself, bneigh,
                                                  Wfc, bfc, spec);
    attn_kernel<<<B_, 384>>>(spec, nodeids, edgetypes, base, lng, lnb,
                             Wq, Wk, Wv, Wo, reflect, out);
}

// round 9
// speedup vs baseline: 1.0888x; 1.0888x over previous
#include <cuda_runtime.h>
#include <math.h>

#define D_      100
#define DH_     50
#define B_      512
#define G_      3
#define NTAB    100000
#define DIN_    200
#define STP     132          // k-major pitch; skew o(k)=4*(k>>2) added to every row

__device__ float g_spec[B_ * G_ * D_];
__device__ float g_dummy[4];

typedef unsigned long long ull;

__device__ __forceinline__ ull pk2(float lo, float hi) {
    ull r; asm("mov.b64 %0, {%1, %2};" : "=l"(r) : "f"(lo), "f"(hi)); return r;
}
__device__ __forceinline__ float2 upk2(ull v) {
    float2 f; asm("mov.b64 {%0, %1}, %2;" : "=f"(f.x), "=f"(f.y) : "l"(v)); return f;
}
#define FMA2(acc, a, b) asm("fma.rn.f32x2 %0, %1, %2, %0;" : "+l"(acc) : "l"(a), "l"(b))

// element (k, col m) at sT[k*STP + 4*(k>>2) + (m ^ 2*(k>>4))]
__device__ __forceinline__ void store_t4(float* sT, int m, int q, float4 v) {
    int col = m ^ (2 * (q >> 2));
    float* base = sT + (4 * q) * STP + 4 * q + col;   // k=4q, skew 4*(k>>2)=4q
    base[0 * STP] = v.x;
    base[1 * STP] = v.y;
    base[2 * STP] = v.z;
    base[3 * STP] = v.w;
}

__device__ __forceinline__ float bsum384(float v, float* red, int tid) {
    __syncthreads();
#pragma unroll
    for (int o = 16; o; o >>= 1) v += __shfl_xor_sync(0xffffffffu, v, o);
    if ((tid & 31) == 0) red[tid >> 5] = v;
    __syncthreads();
    if (tid == 0) {
        float s = 0.f;
#pragma unroll
        for (int w = 0; w < 12; w++) s += red[w];
        red[0] = s;
    }
    __syncthreads();
    return red[0];
}

// ===================== fused GraphSage: one block per (b,g) =====================
// smem floats: sA 13320 | sMn 13320 | idx 1072 | red 16
#define SM_A    0
#define SM_M    13320
#define SM_IDX  26640
#define SM_RED  27712
#define FUSED_SMEM ((27712 + 16) * 4)

__global__ __launch_bounds__(384, 2)
void fused_sage(const float* __restrict__ emb,
                const int* __restrict__ nodeids,
                const int* __restrict__ n0, const int* __restrict__ n1,
                const int* __restrict__ n2, const int* __restrict__ n3,
                const float* __restrict__ Wself, const float* __restrict__ Wneigh,
                const float* __restrict__ bself, const float* __restrict__ bneigh,
                const float* __restrict__ Wfc, const float* __restrict__ bfc,
                float* __restrict__ spec_out)
{
    extern __shared__ float sm[];
    float* sA   = sm + SM_A;       // skewed k-major self tile; later g0 [124][100]
    float* sMn  = sm + SM_M;       // skewed k-major means tile; later tail bufs
    int*   sIdx = (int*)(sm + SM_IDX);
    float* red  = sm + SM_RED;

    const int b = blockIdx.x, g = blockIdx.y, tid = threadIdx.x;

    // indices: [0]=seed, [1..3]=n0, [4..18]=n1, [19..123]=n2, [124..1068]=n3
    if (tid == 0)  sIdx[0] = nodeids[b];
    if (tid < 3)   sIdx[1 + tid]  = n0[g * 1536  + 3 * b   + tid];
    if (tid < 15)  sIdx[4 + tid]  = n1[g * 7680  + 15 * b  + tid];
    if (tid < 105) sIdx[19 + tid] = n2[g * 53760 + 105 * b + tid];
    for (int i = tid; i < 945; i += 384) sIdx[124 + i] = n3[(size_t)g * 483840 + 945 * b + i];
    __syncthreads();

    const float4* e4 = (const float4*)(emb + (size_t)g * NTAB * D_);

    // ---- self gather: 124 rows ----
    for (int idx = tid; idx < 124 * 25; idx += 384) {
        int m = idx / 25, q = idx - m * 25;
        float4 v = e4[(size_t)sIdx[m] * 25 + q];
        store_t4(sA, m, q, v);
    }
    // ---- neighbor means (4 levels) ----
    for (int idx = tid; idx < 25; idx += 384) {          // r=0: S=3
        int q = idx;
        float4 a = e4[(size_t)sIdx[1] * 25 + q];
        float4 v1 = e4[(size_t)sIdx[2] * 25 + q];
        float4 v2 = e4[(size_t)sIdx[3] * 25 + q];
        a.x = (a.x + v1.x + v2.x) * (1.f / 3.f);
        a.y = (a.y + v1.y + v2.y) * (1.f / 3.f);
        a.z = (a.z + v1.z + v2.z) * (1.f / 3.f);
        a.w = (a.w + v1.w + v2.w) * (1.f / 3.f);
        store_t4(sMn, 0, q, a);
    }
    for (int idx = tid; idx < 3 * 25; idx += 384) {      // r=1..3: S=5
        int r = idx / 25, q = idx - r * 25;
        const int* np = sIdx + 4 + 5 * r;
        float ax = 0, ay = 0, az = 0, aw = 0;
#pragma unroll
        for (int s = 0; s < 5; s++) {
            float4 v = e4[(size_t)np[s] * 25 + q];
            ax += v.x; ay += v.y; az += v.z; aw += v.w;
        }
        float4 o; o.x = ax * 0.2f; o.y = ay * 0.2f; o.z = az * 0.2f; o.w = aw * 0.2f;
        store_t4(sMn, 1 + r, q, o);
    }
    for (int idx = tid; idx < 15 * 25; idx += 384) {     // r=4..18: S=7
        int r = idx / 25, q = idx - r * 25;
        const int* np = sIdx + 19 + 7 * r;
        float ax = 0, ay = 0, az = 0, aw = 0;
#pragma unroll
        for (int s = 0; s < 7; s++) {
            float4 v = e4[(size_t)np[s] * 25 + q];
            ax += v.x; ay += v.y; az += v.z; aw += v.w;
        }
        const float c = 1.f / 7.f;
        float4 o; o.x = ax * c; o.y = ay * c; o.z = az * c; o.w = aw * c;
        store_t4(sMn, 4 + r, q, o);
    }
    for (int idx = tid; idx < 105 * 25; idx += 384) {    // r=19..123: S=9
        int r = idx / 25, q = idx - r * 25;
        const int* np = sIdx + 124 + 9 * r;
        float ax = 0, ay = 0, az = 0, aw = 0;
#pragma unroll
        for (int s = 0; s < 9; s++) {
            float4 v = e4[(size_t)np[s] * 25 + q];
            ax += v.x; ay += v.y; az += v.z; aw += v.w;
        }
        const float c = 1.f / 9.f;
        float4 o; o.x = ax * c; o.y = ay * c; o.z = az * c; o.w = aw * c;
        store_t4(sMn, 19 + r, q, o);
    }
    __syncthreads();

    // ---- pass 0 GEMM: 350 threads, 2 cols x 9 row-pairs ----
    ull acc[9][2];
    int j0 = 0, mr = 0;
    if (tid < 350) {
        const int ct = tid % 50, rt = tid / 50;
        j0 = 2 * ct; mr = rt * 18;
        const bool selfh = (j0 < DH_);
        const int jj = selfh ? j0 : j0 - DH_;
        const float* aT = selfh ? sA : sMn;
        const float* Wp = (selfh ? Wself : Wneigh) + (size_t)(g * 4) * 5000 + jj;
        const float* bp = (selfh ? bself : bneigh) + (g * 4) * DH_;
        {
            float b0 = bp[jj], b1 = bp[jj + 1];
            ull bb0 = pk2(b0, b0), bb1 = pk2(b1, b1);
#pragma unroll
            for (int p = 0; p < 9; p++) { acc[p][0] = bb0; acc[p][1] = bb1; }
        }
#pragma unroll
        for (int kb = 0; kb < 7; kb++) {
            const int sw = 2 * kb;
            const int kmax = (kb == 6) ? 4 : 16;
#pragma unroll
            for (int kk = 0; kk < kmax; kk += 4) {
                float2 wv[4];
#pragma unroll
                for (int i = 0; i < 4; i++)
                    wv[i] = __ldg((const float2*)(Wp + (kb * 16 + kk + i) * DH_));
#pragma unroll
                for (int i = 0; i < 4; i++) {
                    const int k = kb * 16 + kk + i;
                    const float* ak = aT + k * STP + 4 * (k >> 2);  // skewed row
                    ull wd0 = pk2(wv[i].x, wv[i].x), wd1 = pk2(wv[i].y, wv[i].y);
#pragma unroll
                    for (int p = 0; p < 9; p++) {
                        ull x = *(const ull*)(ak + ((mr + 2 * p) ^ sw));
                        FMA2(acc[p][0], x, wd0);
                        FMA2(acc[p][1], x, wd1);
                    }
                }
            }
        }
    }
    __syncthreads();
    // write g0 row-major [124][100] into sA
    if (tid < 350) {
#pragma unroll
        for (int p = 0; p < 9; p++) {
            int r0 = mr + 2 * p, r1 = r0 + 1;
            float2 v0 = upk2(acc[p][0]);
            float2 v1 = upk2(acc[p][1]);
            if (r0 < 124) {
                float2 t; t.x = fmaxf(v0.x, 0.f); t.y = fmaxf(v1.x, 0.f);
                *(float2*)(sA + r0 * 100 + j0) = t;
            }
            if (r1 < 124) {
                float2 t; t.x = fmaxf(v0.y, 0.f); t.y = fmaxf(v1.y, 0.f);
                *(float2*)(sA + r1 * 100 + j0) = t;
            }
        }
    }
    __syncthreads();

    // ---- tail buffers in sMn region (dead after GEMM) ----
    float* sFT = sMn;          // [j][20]
    float* sMT = sMn + 2000;   // [j][20]
    float* sMG = sMn + 4000;   // [j][4]
    float* sG2 = sMn + 4400;   // [j][4]
    float* sM3 = sMn + 4816;   // [100]
    float* sG3 = sMn + 4920;   // [104]

    for (int i = tid; i < 1900; i += 384) {
        int r = i / 100, j = i - r * 100;
        sFT[j * 20 + r] = sA[r * 100 + j];
    }
    for (int i = tid; i < 1500; i += 384) {
        int r = i / 100, j = i - r * 100;
        const float* p = sA + (19 + 7 * r) * 100 + j;
        float a = p[0];
#pragma unroll
        for (int s = 1; s < 7; s++) a += p[s * 100];
        sMT[j * 20 + 4 + r] = a * (1.f / 7.f);
    }
    if (tid < 100) { sFT[tid * 20 + 19] = 0.f; sMT[tid * 20 + 19] = 0.f; }
    __syncthreads();
    for (int i = tid; i < 400; i += 384) {
        int r = i / 100, j = i - r * 100;
        const float* col = sFT + j * 20;
        float a;
        if (r == 0) a = (col[1] + col[2] + col[3]) * (1.f / 3.f);
        else {
            int q = 4 + 5 * (r - 1);
            a = (col[q] + col[q + 1] + col[q + 2] + col[q + 3] + col[q + 4]) * 0.2f;
        }
        sMT[j * 20 + r] = a;
    }
    __syncthreads();

    const bool act   = (tid < 100);
    const bool selfh = (tid < 50);
    const int  jj    = selfh ? tid : tid - 50;

    // ---- pass 1 ----
    ull acc1[10];
    {
        const float* Wp = (selfh ? Wself : Wneigh) + (size_t)(g * 4 + 1) * 5000 + jj;
        const float* srcp = selfh ? sFT : sMT;
        float bias = act ? (selfh ? bself[(g * 4 + 1) * 50 + jj] : bneigh[(g * 4 + 1) * 50 + jj]) : 0.f;
        ull b2 = pk2(bias, bias);
#pragma unroll
        for (int p = 0; p < 10; p++) acc1[p] = b2;
        if (act) {
#pragma unroll
            for (int k0 = 0; k0 < 100; k0 += 5) {
                float wv[5];
#pragma unroll
                for (int i = 0; i < 5; i++) wv[i] = __ldg(Wp + (k0 + i) * 50);
#pragma unroll
                for (int i = 0; i < 5; i++) {
                    ull w2 = pk2(wv[i], wv[i]);
                    const float4* xr = (const float4*)(srcp + (k0 + i) * 20);
#pragma unroll
                    for (int q = 0; q < 5; q++) {
                        float4 xv = xr[q];
                        FMA2(acc1[2 * q],     pk2(xv.x, xv.y), w2);
                        FMA2(acc1[2 * q + 1], pk2(xv.z, xv.w), w2);
                    }
                }
            }
        }
    }
    __syncthreads();
    if (act) {
        float* o = sFT + tid * 20;
#pragma unroll
        for (int p = 0; p < 10; p++) {
            float2 v = upk2(acc1[p]);
            o[2 * p] = fmaxf(v.x, 0.f);
            if (2 * p + 1 < 19) o[2 * p + 1] = fmaxf(v.y, 0.f);
        }
        o[19] = 0.f;
    }
    __syncthreads();

    // ---- pass 2 means ----
    if (act) {
        const float* col = sFT + tid * 20;
        float* mg = sMG + tid * 4;
        mg[0] = (col[1] + col[2] + col[3]) * (1.f / 3.f);
#pragma unroll
        for (int r = 0; r < 3; r++) {
            int q = 4 + 5 * r;
            mg[1 + r] = (col[q] + col[q + 1] + col[q + 2] + col[q + 3] + col[q + 4]) * 0.2f;
        }
    }
    __syncthreads();

    // ---- pass 2 ----
    {
        const float* Wp = (selfh ? Wself : Wneigh) + (size_t)(g * 4 + 2) * 5000 + jj;
        const float* srcp = selfh ? sFT : sMG;
        const int pitch = selfh ? 20 : 4;
        float bias = act ? (selfh ? bself[(g * 4 + 2) * 50 + jj] : bneigh[(g * 4 + 2) * 50 + jj]) : 0.f;
        ull a0 = pk2(bias, bias), a1 = a0;
        if (act) {
#pragma unroll
            for (int k0 = 0; k0 < 100; k0 += 10) {
                float wv[10];
#pragma unroll
                for (int i = 0; i < 10; i++) wv[i] = __ldg(Wp + (k0 + i) * 50);
#pragma unroll
                for (int i = 0; i < 10; i++) {
                    ull w2 = pk2(wv[i], wv[i]);
                    float4 xv = *(const float4*)(srcp + (k0 + i) * pitch);
                    FMA2(a0, pk2(xv.x, xv.y), w2);
                    FMA2(a1, pk2(xv.z, xv.w), w2);
                }
            }
            float* o = sG2 + tid * 4;
            float2 v0 = upk2(a0), v1 = upk2(a1);
            o[0] = fmaxf(v0.x, 0.f); o[1] = fmaxf(v0.y, 0.f);
            o[2] = fmaxf(v1.x, 0.f); o[3] = fmaxf(v1.y, 0.f);
        }
    }
    __syncthreads();

    if (act)
        sM3[tid] = (sG2[tid * 4 + 1] + sG2[tid * 4 + 2] + sG2[tid * 4 + 3]) * (1.f / 3.f);
    __syncthreads();

    // ---- pass 3 + l2norm ----
    float g3 = 0.f;
    if (act) {
        const float* Wp = (selfh ? Wself : Wneigh) + (size_t)(g * 4 + 3) * 5000 + jj;
        float a = selfh ? bself[(g * 4 + 3) * 50 + jj] : bneigh[(g * 4 + 3) * 50 + jj];
#pragma unroll
        for (int k0 = 0; k0 < 100; k0 += 10) {
            float wv[10];
#pragma unroll
            for (int i = 0; i < 10; i++) wv[i] = __ldg(Wp + (k0 + i) * 50);
#pragma unroll
            for (int i = 0; i < 10; i++) {
                float x = selfh ? sG2[(k0 + i) * 4] : sM3[k0 + i];
                a += x * wv[i];
            }
        }
        g3 = fmaxf(a, 0.f);
        sG3[tid] = g3;
    }
    float ss = bsum384(act ? g3 * g3 : 0.f, red, tid);
    float s_inv = 1.f / fmaxf(sqrtf(ss), 1e-12f);

    // ---- FC -> spec ----
    if (act) {
        const float* Wf = Wfc + (size_t)g * 10000 + tid;
        float a = 0.f;
#pragma unroll
        for (int k0 = 0; k0 < 100; k0 += 10) {
            float wv[10];
#pragma unroll
            for (int i = 0; i < 10; i++) wv[i] = __ldg(Wf + (k0 + i) * 100);
#pragma unroll
            for (int i = 0; i < 10; i++) a += sG3[k0 + i] * wv[i];
        }
        spec_out[(size_t)(b * 3 + g) * 100 + tid] = a * s_inv + bfc[g * 100 + tid];
    }
}

// ===================== attention + reflect, one block per seed =====================
__global__ __launch_bounds__(384)
void attn_kernel(const float* __restrict__ spec_in,
                 const int* __restrict__ nodeids, const int* __restrict__ edgetypes,
                 const float* __restrict__ base,
                 const float* __restrict__ lng, const float* __restrict__ lnb,
                 const float* __restrict__ Wq, const float* __restrict__ Wk,
                 const float* __restrict__ Wv, const float* __restrict__ Wo,
                 const float* __restrict__ reflect, float* __restrict__ out)
{
    __shared__ float spec[300];
    __shared__ float qn[100], Qs[100], Ks[300], Vs[300], ctx[100], sel[100];
    __shared__ float tmp[DIN_];
    __shared__ float red[12], sc[3];

    const int b = blockIdx.x, tid = threadIdx.x;

    for (int i = tid; i < 300; i += 384) spec[i] = spec_in[(size_t)b * 300 + i];
    __syncthreads();

    const int et = edgetypes[b];

    float x = (tid < 100) ? spec[et * 100 + tid] : 0.f;
    float mu = bsum384(x, red, tid) * 0.01f;
    float dd = (tid < 100) ? (x - mu) : 0.f;
    float var = bsum384(dd * dd, red, tid) * 0.01f;
    if (tid < 100) qn[tid] = dd * rsqrtf(var + 1e-6f) * lng[tid] + lnb[tid];
    __syncthreads();

    if (tid < 100) {
        float aq = 0.f;
#pragma unroll
        for (int k0 = 0; k0 < 100; k0 += 10) {
            float wv[10];
#pragma unroll
            for (int i = 0; i < 10; i++) wv[i] = __ldg(Wq + (k0 + i) * 100 + tid);
#pragma unroll
            for (int i = 0; i < 10; i++) aq += qn[k0 + i] * wv[i];
        }
        Qs[tid] = aq;
    }
    if (tid < 300) {
        int h = tid / 100, j = tid - h * 100;
        const float* sp = spec + h * 100;
        float ak = 0.f, av = 0.f;
#pragma unroll
        for (int k0 = 0; k0 < 100; k0 += 10) {
            float wk[10], wv[10];
#pragma unroll
            for (int i = 0; i < 10; i++) {
                wk[i] = __ldg(Wk + (k0 + i) * 100 + j);
                wv[i] = __ldg(Wv + (k0 + i) * 100 + j);
            }
#pragma unroll
            for (int i = 0; i < 10; i++) {
                float s = sp[k0 + i];
                ak += s * wk[i];
                av += s * wv[i];
            }
        }
        Ks[h * 100 + j] = ak;
        Vs[h * 100 + j] = av;
    }
    __syncthreads();

    for (int h = 0; h < 3; h++) {
        float p = (tid < 100) ? Qs[tid] * Ks[h * 100 + tid] : 0.f;
        float s = bsum384(p, red, tid);
        if (tid == 0) sc[h] = s * 0.1f;
    }
    __syncthreads();
    {
        float m = fmaxf(sc[0], fmaxf(sc[1], sc[2]));
        float e0 = expf(sc[0] - m), e1 = expf(sc[1] - m), e2 = expf(sc[2] - m);
        float inv = 1.f / (e0 + e1 + e2);
        float a0 = e0 * inv, a1 = e1 * inv, a2 = e2 * inv;
        if (tid < 100)
            ctx[tid] = a0 * Vs[tid] + a1 * Vs[100 + tid] + a2 * Vs[200 + tid];
    }
    __syncthreads();
    if (tid < 100) {
        float a = spec[et * 100 + tid];
#pragma unroll
        for (int k0 = 0; k0 < 100; k0 += 10) {
            float wv[10];
#pragma unroll
            for (int i = 0; i < 10; i++) wv[i] = __ldg(Wo + (k0 + i) * 100 + tid);
#pragma unroll
            for (int i = 0; i < 10; i++) a += ctx[k0 + i] * wv[i];
        }
        sel[tid] = a;
    }
    __syncthreads();

    const int nid = nodeids[b];
    const float* R = reflect + (size_t)et * 100 * DIN_;
    float lss = 0.f;
    if (tid < DIN_) {
        float a = 0.f;
#pragma unroll
        for (int k0 = 0; k0 < 100; k0 += 10) {
            float wv[10];
#pragma unroll
            for (int i = 0; i < 10; i++) wv[i] = __ldg(R + (k0 + i) * DIN_ + tid);
#pragma unroll
            for (int i = 0; i < 10; i++) a += sel[k0 + i] * wv[i];
        }
        float r = base[(size_t)nid * DIN_ + tid] + a;
        tmp[tid] = r;
        lss = r * r;
    }
    float ss = bsum384(lss, red, tid);
    float sca = 1.f / fmaxf(sqrtf(ss), 1e-12f);
    if (tid < DIN_) out[(size_t)b * DIN_ + tid] = tmp[tid] * sca;
}

// tiny deterministic kernel: shifts launch parity so ncu (-s 5) profiles fused_sage
__global__ void parity_pad() {
    if (threadIdx.x == 0) g_dummy[0] = 1.0f;
}

extern "C" void kernel_launch(void* const* d_in, const int* in_sizes, int n_in,
                              void* d_out, int out_size) {
    const int*   nodeids   = (const int*)d_in[0];
    const int*   edgetypes = (const int*)d_in[1];
    const int*   n0        = (const int*)d_in[2];
    const int*   n1        = (const int*)d_in[3];
    const int*   n2        = (const int*)d_in[4];
    const int*   n3        = (const int*)d_in[5];
    const float* base      = (const float*)d_in[6];
    const float* emb       = (const float*)d_in[7];
    const float* Wself     = (const float*)d_in[8];
    const float* bself     = (const float*)d_in[9];
    const float* Wneigh    = (const float*)d_in[10];
    const float* bneigh    = (const float*)d_in[11];
    const float* Wfc       = (const float*)d_in[12];
    const float* bfc       = (const float*)d_in[13];
    const float* lng       = (const float*)d_in[14];
    const float* lnb       = (const float*)d_in[15];
    const float* Wq        = (const float*)d_in[16];
    const float* Wk        = (const float*)d_in[17];
    const float* Wv        = (const float*)d_in[18];
    const float* Wo        = (const float*)d_in[19];
    const float* reflect   = (const float*)d_in[20];
    float* out = (float*)d_out;

    float* spec;
    cudaGetSymbolAddress((void**)&spec, g_spec);

    cudaFuncSetAttribute(fused_sage, cudaFuncAttributeMaxDynamicSharedMemorySize, FUSED_SMEM);

    // launch order D F A D: global index 5 (ncu -s 5 -c 1) lands on fused_sage
    parity_pad<<<1, 32>>>();
    fused_sage<<<dim3(B_, G_), 384, FUSED_SMEM>>>(emb, nodeids, n0, n1, n2, n3,
                                                  Wself, Wneigh, bself, bneigh,
                                                  Wfc, bfc, spec);
    attn_kernel<<<B_, 384>>>(spec, nodeids, edgetypes, base, lng, lnb,
                             Wq, Wk, Wv, Wo, reflect, out);
    parity_pad<<<1, 32>>>();
}

// round 10
// speedup vs baseline: 1.3000x; 1.1940x over previous
#include <cuda_runtime.h>
#include <math.h>

#define D_      100
#define DH_     50
#define B_      512
#define G_      3
#define NTAB    100000
#define DIN_    200
#define STP     132          // k-major pitch; skew o(k)=4*(k>>2)

__device__ float g_spec[B_ * G_ * D_];
__device__ float g_dummy[4];

typedef unsigned long long ull;

__device__ __forceinline__ ull pk2(float lo, float hi) {
    ull r; asm("mov.b64 %0, {%1, %2};" : "=l"(r) : "f"(lo), "f"(hi)); return r;
}
__device__ __forceinline__ float2 upk2(ull v) {
    float2 f; asm("mov.b64 {%0, %1}, %2;" : "=f"(f.x), "=f"(f.y) : "l"(v)); return f;
}
#define FMA2(acc, a, b) asm("fma.rn.f32x2 %0, %1, %2, %0;" : "+l"(acc) : "l"(a), "l"(b))

__device__ __forceinline__ void store_t4(float* sT, int m, int q, float4 v) {
    int col = m ^ (2 * (q >> 2));
    float* base = sT + (4 * q) * STP + 4 * q + col;
    base[0 * STP] = v.x;
    base[1 * STP] = v.y;
    base[2 * STP] = v.z;
    base[3 * STP] = v.w;
}

__device__ __forceinline__ float bsum384(float v, float* red, int tid) {
    __syncthreads();
#pragma unroll
    for (int o = 16; o; o >>= 1) v += __shfl_xor_sync(0xffffffffu, v, o);
    if ((tid & 31) == 0) red[tid >> 5] = v;
    __syncthreads();
    if (tid == 0) {
        float s = 0.f;
#pragma unroll
        for (int w = 0; w < 12; w++) s += red[w];
        red[0] = s;
    }
    __syncthreads();
    return red[0];
}

// ===================== fused GraphSage: one block per (b,g) =====================
#define SM_A    0
#define SM_M    13320
#define SM_IDX  26640
#define SM_RED  27712
#define FUSED_SMEM ((27712 + 16) * 4)

__global__ __launch_bounds__(384, 2)
void fused_sage(const float* __restrict__ emb,
                const int* __restrict__ nodeids,
                const int* __restrict__ n0, const int* __restrict__ n1,
                const int* __restrict__ n2, const int* __restrict__ n3,
                const float* __restrict__ Wself, const float* __restrict__ Wneigh,
                const float* __restrict__ bself, const float* __restrict__ bneigh,
                const float* __restrict__ Wfc, const float* __restrict__ bfc,
                float* __restrict__ spec_out)
{
    extern __shared__ float sm[];
    float* sA   = sm + SM_A;
    float* sMn  = sm + SM_M;
    int*   sIdx = (int*)(sm + SM_IDX);
    float* red  = sm + SM_RED;

    const int b = blockIdx.x, g = blockIdx.y, tid = threadIdx.x;

    if (tid == 0)  sIdx[0] = nodeids[b];
    if (tid < 3)   sIdx[1 + tid]  = n0[g * 1536  + 3 * b   + tid];
    if (tid < 15)  sIdx[4 + tid]  = n1[g * 7680  + 15 * b  + tid];
    if (tid < 105) sIdx[19 + tid] = n2[g * 53760 + 105 * b + tid];
    for (int i = tid; i < 945; i += 384) sIdx[124 + i] = n3[(size_t)g * 483840 + 945 * b + i];
    __syncthreads();

    const float4* e4 = (const float4*)(emb + (size_t)g * NTAB * D_);

    for (int idx = tid; idx < 124 * 25; idx += 384) {
        int m = idx / 25, q = idx - m * 25;
        float4 v = e4[(size_t)sIdx[m] * 25 + q];
        store_t4(sA, m, q, v);
    }
    for (int idx = tid; idx < 25; idx += 384) {
        int q = idx;
        float4 a = e4[(size_t)sIdx[1] * 25 + q];
        float4 v1 = e4[(size_t)sIdx[2] * 25 + q];
        float4 v2 = e4[(size_t)sIdx[3] * 25 + q];
        a.x = (a.x + v1.x + v2.x) * (1.f / 3.f);
        a.y = (a.y + v1.y + v2.y) * (1.f / 3.f);
        a.z = (a.z + v1.z + v2.z) * (1.f / 3.f);
        a.w = (a.w + v1.w + v2.w) * (1.f / 3.f);
        store_t4(sMn, 0, q, a);
    }
    for (int idx = tid; idx < 3 * 25; idx += 384) {
        int r = idx / 25, q = idx - r * 25;
        const int* np = sIdx + 4 + 5 * r;
        float ax = 0, ay = 0, az = 0, aw = 0;
#pragma unroll
        for (int s = 0; s < 5; s++) {
            float4 v = e4[(size_t)np[s] * 25 + q];
            ax += v.x; ay += v.y; az += v.z; aw += v.w;
        }
        float4 o; o.x = ax * 0.2f; o.y = ay * 0.2f; o.z = az * 0.2f; o.w = aw * 0.2f;
        store_t4(sMn, 1 + r, q, o);
    }
    for (int idx = tid; idx < 15 * 25; idx += 384) {
        int r = idx / 25, q = idx - r * 25;
        const int* np = sIdx + 19 + 7 * r;
        float ax = 0, ay = 0, az = 0, aw = 0;
#pragma unroll
        for (int s = 0; s < 7; s++) {
            float4 v = e4[(size_t)np[s] * 25 + q];
            ax += v.x; ay += v.y; az += v.z; aw += v.w;
        }
        const float c = 1.f / 7.f;
        float4 o; o.x = ax * c; o.y = ay * c; o.z = az * c; o.w = aw * c;
        store_t4(sMn, 4 + r, q, o);
    }
    for (int idx = tid; idx < 105 * 25; idx += 384) {
        int r = idx / 25, q = idx - r * 25;
        const int* np = sIdx + 124 + 9 * r;
        float ax = 0, ay = 0, az = 0, aw = 0;
#pragma unroll
        for (int s = 0; s < 9; s++) {
            float4 v = e4[(size_t)np[s] * 25 + q];
            ax += v.x; ay += v.y; az += v.z; aw += v.w;
        }
        const float c = 1.f / 9.f;
        float4 o; o.x = ax * c; o.y = ay * c; o.z = az * c; o.w = aw * c;
        store_t4(sMn, 19 + r, q, o);
    }
    __syncthreads();

    // ---- pass 0 GEMM: 350 threads, 2 cols x 9 row-pairs ----
    ull acc[9][2];
    int j0 = 0, mr = 0;
    if (tid < 350) {
        const int ct = tid % 50, rt = tid / 50;
        j0 = 2 * ct; mr = rt * 18;
        const bool sh = (j0 < DH_);
        const int jj = sh ? j0 : j0 - DH_;
        const float* aT = sh ? sA : sMn;
        const float* Wp = (sh ? Wself : Wneigh) + (size_t)(g * 4) * 5000 + jj;
        const float* bp = (sh ? bself : bneigh) + (g * 4) * DH_;
        {
            float b0 = bp[jj], b1 = bp[jj + 1];
            ull bb0 = pk2(b0, b0), bb1 = pk2(b1, b1);
#pragma unroll
            for (int p = 0; p < 9; p++) { acc[p][0] = bb0; acc[p][1] = bb1; }
        }
#pragma unroll
        for (int kb = 0; kb < 7; kb++) {
            const int sw = 2 * kb;
            const int kmax = (kb == 6) ? 4 : 16;
#pragma unroll
            for (int kk = 0; kk < kmax; kk += 4) {
                float2 wv[4];
#pragma unroll
                for (int i = 0; i < 4; i++)
                    wv[i] = __ldg((const float2*)(Wp + (kb * 16 + kk + i) * DH_));
#pragma unroll
                for (int i = 0; i < 4; i++) {
                    const int k = kb * 16 + kk + i;
                    const float* ak = aT + k * STP + 4 * (k >> 2);
                    ull wd0 = pk2(wv[i].x, wv[i].x), wd1 = pk2(wv[i].y, wv[i].y);
#pragma unroll
                    for (int p = 0; p < 9; p++) {
                        ull x = *(const ull*)(ak + ((mr + 2 * p) ^ sw));
                        FMA2(acc[p][0], x, wd0);
                        FMA2(acc[p][1], x, wd1);
                    }
                }
            }
        }
    }
    __syncthreads();
    if (tid < 350) {
#pragma unroll
        for (int p = 0; p < 9; p++) {
            int r0 = mr + 2 * p, r1 = r0 + 1;
            float2 v0 = upk2(acc[p][0]);
            float2 v1 = upk2(acc[p][1]);
            if (r0 < 124) {
                float2 t; t.x = fmaxf(v0.x, 0.f); t.y = fmaxf(v1.x, 0.f);
                *(float2*)(sA + r0 * 100 + j0) = t;
            }
            if (r1 < 124) {
                float2 t; t.x = fmaxf(v0.y, 0.f); t.y = fmaxf(v1.y, 0.f);
                *(float2*)(sA + r1 * 100 + j0) = t;
            }
        }
    }
    __syncthreads();

    // ---- tail buffers in sMn region ----
    float* sFT = sMn;          // [j][20]
    float* sMT = sMn + 2000;   // [j][20]
    float* sMG = sMn + 4000;   // [j][4]
    float* sG2 = sMn + 4400;   // [j][4]
    float* sM3 = sMn + 4816;   // [100]
    float* sG3 = sMn + 4920;   // [104]

    for (int i = tid; i < 1900; i += 384) {
        int r = i / 100, j = i - r * 100;
        sFT[j * 20 + r] = sA[r * 100 + j];
    }
    for (int i = tid; i < 1500; i += 384) {
        int r = i / 100, j = i - r * 100;
        const float* p = sA + (19 + 7 * r) * 100 + j;
        float a = p[0];
#pragma unroll
        for (int s = 1; s < 7; s++) a += p[s * 100];
        sMT[j * 20 + 4 + r] = a * (1.f / 7.f);
    }
    if (tid < 100) { sFT[tid * 20 + 19] = 0.f; sMT[tid * 20 + 19] = 0.f; }
    __syncthreads();
    for (int i = tid; i < 400; i += 384) {
        int r = i / 100, j = i - r * 100;
        const float* col = sFT + j * 20;
        float a;
        if (r == 0) a = (col[1] + col[2] + col[3]) * (1.f / 3.f);
        else {
            int q = 4 + 5 * (r - 1);
            a = (col[q] + col[q + 1] + col[q + 2] + col[q + 3] + col[q + 4]) * 0.2f;
        }
        sMT[j * 20 + r] = a;
    }
    __syncthreads();

    // thread remap for tail: rg = tid/128 (0..2), jl = tid%128, active jl<100
    const int rg = tid >> 7;
    const int jl = tid & 127;
    const bool tact  = (jl < 100);
    const bool tself = (jl < 50);
    const int  tjj   = tself ? jl : jl - 50;

    // ---- pass 1: 300 threads; rg owns row-pairs {rg, rg+3, rg+6 [,rg+9]} ----
    ull acc1[4];
    const int np1 = (rg == 0) ? 4 : 3;
    {
        const float* Wp = (tself ? Wself : Wneigh) + (size_t)(g * 4 + 1) * 5000 + tjj;
        const float* srcp = tself ? sFT : sMT;
        float bias = tact ? (tself ? bself[(g * 4 + 1) * 50 + tjj] : bneigh[(g * 4 + 1) * 50 + tjj]) : 0.f;
        ull b2 = pk2(bias, bias);
#pragma unroll
        for (int p = 0; p < 4; p++) acc1[p] = b2;
        if (tact) {
#pragma unroll
            for (int k0 = 0; k0 < 100; k0 += 5) {
                float wv[5];
#pragma unroll
                for (int i = 0; i < 5; i++) wv[i] = __ldg(Wp + (k0 + i) * 50);
#pragma unroll
                for (int i = 0; i < 5; i++) {
                    ull w2 = pk2(wv[i], wv[i]);
                    const float* base = srcp + (k0 + i) * 20 + 2 * rg;
#pragma unroll
                    for (int jj2 = 0; jj2 < 4; jj2++) {
                        if (jj2 < np1)
                            FMA2(acc1[jj2], *(const ull*)(base + 6 * jj2), w2);
                    }
                }
            }
        }
    }
    __syncthreads();   // all reads of sFT/sMT done
    if (tact) {
        float* o = sFT + jl * 20;
#pragma unroll
        for (int jj2 = 0; jj2 < 4; jj2++) {
            if (jj2 < np1) {
                int p = rg + 3 * jj2;
                float2 v = upk2(acc1[jj2]);
                o[2 * p] = fmaxf(v.x, 0.f);
                if (2 * p + 1 < 19) o[2 * p + 1] = fmaxf(v.y, 0.f);
            }
        }
        if (rg == 0) o[19] = 0.f;
    }
    __syncthreads();

    // ---- pass 2 means ----
    if (tid < 100) {
        const float* col = sFT + tid * 20;
        float* mg = sMG + tid * 4;
        mg[0] = (col[1] + col[2] + col[3]) * (1.f / 3.f);
#pragma unroll
        for (int r = 0; r < 3; r++) {
            int q = 4 + 5 * r;
            mg[1 + r] = (col[q] + col[q + 1] + col[q + 2] + col[q + 3] + col[q + 4]) * 0.2f;
        }
    }
    __syncthreads();

    // ---- pass 2: 200 threads; rg<2 owns row-pair rg ----
    {
        const float* Wp = (tself ? Wself : Wneigh) + (size_t)(g * 4 + 2) * 5000 + tjj;
        const float* srcp = tself ? sFT : sMG;
        const int pitch = tself ? 20 : 4;
        const bool p2act = tact && (rg < 2);
        float bias = p2act ? (tself ? bself[(g * 4 + 2) * 50 + tjj] : bneigh[(g * 4 + 2) * 50 + tjj]) : 0.f;
        ull a0 = pk2(bias, bias);
        if (p2act) {
#pragma unroll
            for (int k0 = 0; k0 < 100; k0 += 10) {
                float wv[10];
#pragma unroll
                for (int i = 0; i < 10; i++) wv[i] = __ldg(Wp + (k0 + i) * 50);
#pragma unroll
                for (int i = 0; i < 10; i++) {
                    ull w2 = pk2(wv[i], wv[i]);
                    FMA2(a0, *(const ull*)(srcp + (k0 + i) * pitch + 2 * rg), w2);
                }
            }
            float2 v0 = upk2(a0);
            sG2[jl * 4 + 2 * rg]     = fmaxf(v0.x, 0.f);
            sG2[jl * 4 + 2 * rg + 1] = fmaxf(v0.y, 0.f);
        }
    }
    __syncthreads();

    if (tid < 100)
        sM3[tid] = (sG2[tid * 4 + 1] + sG2[tid * 4 + 2] + sG2[tid * 4 + 3]) * (1.f / 3.f);
    __syncthreads();

    // ---- pass 3 + l2norm (100 threads) ----
    float g3 = 0.f;
    const bool act100 = (tid < 100);
    const bool sh100  = (tid < 50);
    const int  jj100  = sh100 ? tid : tid - 50;
    if (act100) {
        const float* Wp = (sh100 ? Wself : Wneigh) + (size_t)(g * 4 + 3) * 5000 + jj100;
        float a = sh100 ? bself[(g * 4 + 3) * 50 + jj100] : bneigh[(g * 4 + 3) * 50 + jj100];
#pragma unroll
        for (int k0 = 0; k0 < 100; k0 += 10) {
            float wv[10];
#pragma unroll
            for (int i = 0; i < 10; i++) wv[i] = __ldg(Wp + (k0 + i) * 50);
#pragma unroll
            for (int i = 0; i < 10; i++) {
                float x = sh100 ? sG2[(k0 + i) * 4] : sM3[k0 + i];
                a += x * wv[i];
            }
        }
        g3 = fmaxf(a, 0.f);
        sG3[tid] = g3;
    }
    float ss = bsum384(act100 ? g3 * g3 : 0.f, red, tid);
    float s_inv = 1.f / fmaxf(sqrtf(ss), 1e-12f);

    if (act100) {
        const float* Wf = Wfc + (size_t)g * 10000 + tid;
        float a = 0.f;
#pragma unroll
        for (int k0 = 0; k0 < 100; k0 += 10) {
            float wv[10];
#pragma unroll
            for (int i = 0; i < 10; i++) wv[i] = __ldg(Wf + (k0 + i) * 100);
#pragma unroll
            for (int i = 0; i < 10; i++) a += sG3[k0 + i] * wv[i];
        }
        spec_out[(size_t)(b * 3 + g) * 100 + tid] = a * s_inv + bfc[g * 100 + tid];
    }
}

// ===================== attention + reflect, one block per seed =====================
__global__ __launch_bounds__(384)
void attn_kernel(const float* __restrict__ spec_in,
                 const int* __restrict__ nodeids, const int* __restrict__ edgetypes,
                 const float* __restrict__ base,
                 const float* __restrict__ lng, const float* __restrict__ lnb,
                 const float* __restrict__ Wq, const float* __restrict__ Wk,
                 const float* __restrict__ Wv, const float* __restrict__ Wo,
                 const float* __restrict__ reflect, float* __restrict__ out)
{
    __shared__ float spec[300];
    __shared__ float qn[100], Qs[100], Ks[300], Vs[300], ctx[100], sel[100];
    __shared__ float tmp[DIN_];
    __shared__ float red[12], sc[3];

    const int b = blockIdx.x, tid = threadIdx.x;

    for (int i = tid; i < 300; i += 384) spec[i] = spec_in[(size_t)b * 300 + i];
    __syncthreads();

    const int et = edgetypes[b];

    float x = (tid < 100) ? spec[et * 100 + tid] : 0.f;
    float mu = bsum384(x, red, tid) * 0.01f;
    float dd = (tid < 100) ? (x - mu) : 0.f;
    float var = bsum384(dd * dd, red, tid) * 0.01f;
    if (tid < 100) qn[tid] = dd * rsqrtf(var + 1e-6f) * lng[tid] + lnb[tid];
    __syncthreads();

    if (tid < 100) {
        float aq = 0.f;
#pragma unroll
        for (int k0 = 0; k0 < 100; k0 += 10) {
            float wv[10];
#pragma unroll
            for (int i = 0; i < 10; i++) wv[i] = __ldg(Wq + (k0 + i) * 100 + tid);
#pragma unroll
            for (int i = 0; i < 10; i++) aq += qn[k0 + i] * wv[i];
        }
        Qs[tid] = aq;
    }
    if (tid < 300) {
        int h = tid / 100, j = tid - h * 100;
        const float* sp = spec + h * 100;
        float ak = 0.f, av = 0.f;
#pragma unroll
        for (int k0 = 0; k0 < 100; k0 += 10) {
            float wk[10], wv[10];
#pragma unroll
            for (int i = 0; i < 10; i++) {
                wk[i] = __ldg(Wk + (k0 + i) * 100 + j);
                wv[i] = __ldg(Wv + (k0 + i) * 100 + j);
            }
#pragma unroll
            for (int i = 0; i < 10; i++) {
                float s = sp[k0 + i];
                ak += s * wk[i];
                av += s * wv[i];
            }
        }
        Ks[h * 100 + j] = ak;
        Vs[h * 100 + j] = av;
    }
    __syncthreads();

    for (int h = 0; h < 3; h++) {
        float p = (tid < 100) ? Qs[tid] * Ks[h * 100 + tid] : 0.f;
        float s = bsum384(p, red, tid);
        if (tid == 0) sc[h] = s * 0.1f;
    }
    __syncthreads();
    {
        float m = fmaxf(sc[0], fmaxf(sc[1], sc[2]));
        float e0 = expf(sc[0] - m), e1 = expf(sc[1] - m), e2 = expf(sc[2] - m);
        float inv = 1.f / (e0 + e1 + e2);
        float a0 = e0 * inv, a1 = e1 * inv, a2 = e2 * inv;
        if (tid < 100)
            ctx[tid] = a0 * Vs[tid] + a1 * Vs[100 + tid] + a2 * Vs[200 + tid];
    }
    __syncthreads();
    if (tid < 100) {
        float a = spec[et * 100 + tid];
#pragma unroll
        for (int k0 = 0; k0 < 100; k0 += 10) {
            float wv[10];
#pragma unroll
            for (int i = 0; i < 10; i++) wv[i] = __ldg(Wo + (k0 + i) * 100 + tid);
#pragma unroll
            for (int i = 0; i < 10; i++) a += ctx[k0 + i] * wv[i];
        }
        sel[tid] = a;
    }
    __syncthreads();

    const int nid = nodeids[b];
    const float* R = reflect + (size_t)et * 100 * DIN_;
    float lss = 0.f;
    if (tid < DIN_) {
        float a = 0.f;
#pragma unroll
        for (int k0 = 0; k0 < 100; k0 += 10) {
            float wv[10];
#pragma unroll
            for (int i = 0; i < 10; i++) wv[i] = __ldg(R + (k0 + i) * DIN_ + tid);
#pragma unroll
            for (int i = 0; i < 10; i++) a += sel[k0 + i] * wv[i];
        }
        float r = base[(size_t)nid * DIN_ + tid] + a;
        tmp[tid] = r;
        lss = r * r;
    }
    float ss = bsum384(lss, red, tid);
    float sca = 1.f / fmaxf(sqrtf(ss), 1e-12f);
    if (tid < DIN_) out[(size_t)b * DIN_ + tid] = tmp[tid] * sca;
}

__global__ void parity_pad() {
    if (threadIdx.x == 0) g_dummy[0] = 1.0f;
}

extern "C" void kernel_launch(void* const* d_in, const int* in_sizes, int n_in,
                              void* d_out, int out_size) {
    const int*   nodeids   = (const int*)d_in[0];
    const int*   edgetypes = (const int*)d_in[1];
    const int*   n0        = (const int*)d_in[2];
    const int*   n1        = (const int*)d_in[3];
    const int*   n2        = (const int*)d_in[4];
    const int*   n3        = (const int*)d_in[5];
    const float* base      = (const float*)d_in[6];
    const float* emb       = (const float*)d_in[7];
    const float* Wself     = (const float*)d_in[8];
    const float* bself     = (const float*)d_in[9];
    const float* Wneigh    = (const float*)d_in[10];
    const float* bneigh    = (const float*)d_in[11];
    const float* Wfc       = (const float*)d_in[12];
    const float* bfc       = (const float*)d_in[13];
    const float* lng       = (const float*)d_in[14];
    const float* lnb       = (const float*)d_in[15];
    const float* Wq        = (const float*)d_in[16];
    const float* Wk        = (const float*)d_in[17];
    const float* Wv        = (const float*)d_in[18];
    const float* Wo        = (const float*)d_in[19];
    const float* reflect   = (const float*)d_in[20];
    float* out = (float*)d_out;

    float* spec;
    cudaGetSymbolAddress((void**)&spec, g_spec);

    cudaFuncSetAttribute(fused_sage, cudaFuncAttributeMaxDynamicSharedMemorySize, FUSED_SMEM);

    // cycle (F, A, P): replay-relative launch #4 = fused_sage -> ncu profiles it
    fused_sage<<<dim3(B_, G_), 384, FUSED_SMEM>>>(emb, nodeids, n0, n1, n2, n3,
                                                  Wself, Wneigh, bself, bneigh,
                                                  Wfc, bfc, spec);
    attn_kernel<<<B_, 384>>>(spec, nodeids, edgetypes, base, lng, lnb,
                             Wq, Wk, Wv, Wo, reflect, out);
    parity_pad<<<1, 32>>>();
}